// round 12
// baseline (speedup 1.0000x reference)
#include <cuda_runtime.h>

// Problem constants: B=32, S=12, F=128, H=64, K=8, C=64, N=512
#define B_   32
#define S_   12
#define F_   128
#define H_   64
#define K_   8
#define C_   64
#define N_   512
#define KH_  (K_*H_)        // 512
#define WFC_ (N_*C_)        // 32768 floats per Wf row

// Scratch (no device mallocs allowed):
__device__ float g_Who[B_*C_];     // 2048 floats
__device__ float g_wfs[C_*C_];     // WfSum[c'][c], 4096 floats

// Kernel 1 (best-measured config, R2), 96 blocks x 1024 threads, one wave:
//  blocks [0,64):  WfSum[c',:] — each block streams one full 128KB Wf row
//  blocks [64,96): Who[b,:]    — GAT collapse: all N=512 node rows are the
//                  broadcast of x[:, -1, :], so both GAT softmaxes are exactly
//                  uniform and att @ Wh == Wh; a1/a2 drop out entirely.
__global__ __launch_bounds__(1024) void k1(
    const float* __restrict__ x,        // (B, S, F)
    const float* __restrict__ W_heads,  // (K, F, H)
    const float* __restrict__ W_out,    // (K*H, C)
    const float* __restrict__ Wf)       // (C, N*C)
{
    const int t   = threadIdx.x;
    const int bid = blockIdx.x;

    if (bid < C_) {
        // ---- Wf row reduction: the only DRAM-heavy work (8.4 MB total) ----
        __shared__ float4 part4[1024];          // 16 KB
        const int cp = bid;
        const int c4 = t & 15;                  // float4 slot within a 64-float n-row
        const int n0 = t >> 4;                  // 0..63
        const float4* __restrict__ row = (const float4*)(Wf + (size_t)cp * WFC_);
        float4 s = make_float4(0.f, 0.f, 0.f, 0.f);
        #pragma unroll
        for (int i = 0; i < 8; ++i) {           // 8 independent float4 loads (128B in flight)
            float4 v = row[(size_t)(n0 + i * 64) * 16 + c4];
            s.x += v.x; s.y += v.y; s.z += v.z; s.w += v.w;
        }
        part4[t] = s;
        __syncthreads();
        if (t < C_) {
            const float* pf = (const float*)part4;   // pf[n*64 + c]
            float acc = 0.f;
            #pragma unroll
            for (int n0i = 0; n0i < 64; ++n0i) acc += pf[n0i * 64 + t];
            g_wfs[cp * C_ + t] = acc;
        }
    } else {
        // ---- Who[b,:] ----
        __shared__ float xs[F_];
        __shared__ float ws[1024];
        __shared__ float hcat[KH_];
        const int b = bid - C_;
        if (t < F_) xs[t] = x[(b * S_ + (S_ - 1)) * F_ + t];
        __syncthreads();
        {   // Wh[k,h], each output split across 2 threads (64 f's each)
            const int o    = t & 511;
            const int half = t >> 9;
            const int k    = o >> 6;
            const int h    = o & 63;
            const float* wp = W_heads + ((size_t)k * F_ + half * 64) * H_ + h;
            const float* xp = xs + half * 64;
            float acc = 0.f;
            #pragma unroll 8
            for (int f = 0; f < 64; ++f) acc = fmaf(xp[f], wp[(size_t)f * H_], acc);
            ws[t] = acc;
        }
        __syncthreads();
        if (t < KH_) {
            float v = ws[t] + ws[t + 512];
            hcat[t] = v > 0.f ? v : expm1f(v);   // ELU
        }
        __syncthreads();
        {   // Who[c] = sum_j hcat[j] * W_out[j,c], j split 16 ways
            const int c  = t & 63;
            const int j0 = t >> 6;
            float p = 0.f;
            #pragma unroll
            for (int j = j0; j < KH_; j += 16)
                p = fmaf(hcat[j], W_out[(size_t)j * C_ + c], p);
            ws[t] = p;
        }
        __syncthreads();
        if (t < C_) {
            float s2 = 0.f;
            #pragma unroll
            for (int g = 0; g < 16; ++g) s2 += ws[g * 64 + t];
            g_Who[b * C_ + t] = s2;
        }
    }
}

// Kernel 2 (R2 config): 2 blocks x 1024 threads. Stage Who (16 rows) + full
// WfSum into smem, then out[b,c'] = bf[c'] + sum_c Who[b,c] * WfSum[c',c].
__global__ __launch_bounds__(1024) void k2(
    const float* __restrict__ bf,
    float* __restrict__ out)
{
    __shared__ float wfs_s[C_ * 65];     // padded rows: bank-conflict-free
    __shared__ float who_s[16 * C_];
    const int t = threadIdx.x;

    #pragma unroll
    for (int i = t; i < C_ * C_; i += 1024) {
        wfs_s[(i >> 6) * 65 + (i & 63)] = g_wfs[i];
    }
    who_s[t] = g_Who[blockIdx.x * 16 * C_ + t];
    __syncthreads();

    const int bl = t >> 6;       // local batch 0..15
    const int cp = t & 63;
    float acc = bf[cp];
    const float* wr = wfs_s + cp * 65;
    const float* hr = who_s + bl * C_;
    #pragma unroll 8
    for (int c = 0; c < C_; ++c) acc = fmaf(hr[c], wr[c], acc);
    out[(blockIdx.x * 16 + bl) * C_ + cp] = acc;
}

extern "C" void kernel_launch(void* const* d_in, const int* in_sizes, int n_in,
                              void* d_out, int out_size)
{
    const float* x       = (const float*)d_in[0]; // (32,12,128)
    const float* W_heads = (const float*)d_in[1]; // (8,128,64)
    // d_in[2], d_in[3]: a1_heads/a2_heads — unused (uniform softmax)
    const float* W_out   = (const float*)d_in[4]; // (512,64)
    // d_in[5], d_in[6]: a1_out/a2_out — unused
    const float* Wf      = (const float*)d_in[7]; // (64, 32768)
    const float* bf      = (const float*)d_in[8]; // (64,)
    float* out = (float*)d_out;                   // (32,64)

    k1<<<C_ + B_, 1024>>>(x, W_heads, W_out, Wf);
    k2<<<2, 1024>>>(bf, out);
}